// round 13
// baseline (speedup 1.0000x reference)
#include <cuda_runtime.h>
#include <cuda_fp16.h>
#include <mma.h>
#include <cstdint>

using namespace nvcuda;

constexpr int INC  = 768;
constexpr int CAv  = 384;
constexpr int BTv  = 128;
constexpr int Tv   = 16;
constexpr int Hv   = 14;
constexpr int Wv   = 14;
constexpr int Lv   = 197;
constexpr int NP   = 196;
constexpr int MTOT = BTv * NP;       // 25088
constexpr int TILE3D = Tv * NP;      // 3136

// Scratch (device globals — no runtime allocation allowed)
__device__ __half g_xh[(size_t)BTv * Lv * INC];
__device__ __half g_w1h[(size_t)CAv * INC];
__device__ __half g_w2h[(size_t)INC * CAv];
__device__ __half g_h0h[(size_t)CAv * MTOT];       // channel-outer [ca][m]
__device__ __half g_h2h[(size_t)CAv * MTOT];       // channel-outer [ca][m]

// GEMM tiling: BM=BN=128, BK=64, 3-stage cp.async pipeline
#define BK 64
#define SA 72     // half-row stride for [*][64]-half K tiles (144B)
#define SAT 136   // half-row stride for fc2 transposed-A [64][128]
#define PCM 132   // C staging ldm (floats, mult of 4)

constexpr int FC1_ABUF = 128 * SA;                 // 9216 halves
constexpr int FC1_BUF  = 2 * FC1_ABUF;             // 18432 halves/stage
constexpr int FC1_SMEM = 3 * FC1_BUF * 2;          // 110592 B
constexpr int FC2_ABUF = BK * SAT;                 // 8704 halves
constexpr int FC2_BBUF = 128 * SA;                 // 9216 halves
constexpr int FC2_BUF  = FC2_ABUF + FC2_BBUF;      // 17920 halves/stage
constexpr int FC2_SMEM = 3 * FC2_BUF * 2;          // 107520 B

__device__ __forceinline__ void cp16(uint32_t dst, const void* src) {
    asm volatile("cp.async.cg.shared.global [%0], [%1], 16;\n" :: "r"(dst), "l"(src));
}
__device__ __forceinline__ void cp_commit() { asm volatile("cp.async.commit_group;\n"); }
__device__ __forceinline__ void cp_wait1()  { asm volatile("cp.async.wait_group 1;\n"); }
__device__ __forceinline__ uint32_t smem_u32(const void* p) {
    return (uint32_t)__cvta_generic_to_shared(p);
}

// ---------------------------------------------------------------------------
// Merged converter + CLS copy: x->half, w1->half, w2->half, out[CLS]=x[CLS]
// ---------------------------------------------------------------------------
constexpr int NX4 = BTv * Lv * INC / 4;
constexpr int NW4 = CAv * INC / 4;
constexpr int NC4 = BTv * INC / 4;

__global__ __launch_bounds__(256) void cvt_all_kernel(
    const float* __restrict__ x, const float* __restrict__ w1,
    const float* __restrict__ w2, float* __restrict__ out)
{
    int i = blockIdx.x * 256 + threadIdx.x;
    const float* src; __half* dst; size_t off;
    if (i < NX4)                { src = x;  dst = g_xh;  off = (size_t)i; }
    else if (i < NX4 + NW4)     { src = w1; dst = g_w1h; off = (size_t)(i - NX4); }
    else if (i < NX4 + 2 * NW4) { src = w2; dst = g_w2h; off = (size_t)(i - NX4 - NW4); }
    else if (i < NX4 + 2 * NW4 + NC4) {
        int j  = i - NX4 - 2 * NW4;
        int bt = j / (INC / 4);
        int c4 = j - bt * (INC / 4);
        size_t o = (size_t)bt * Lv * INC + (size_t)c4 * 4;
        *reinterpret_cast<float4*>(out + o) = *reinterpret_cast<const float4*>(x + o);
        return;
    }
    else return;
    float4 v = *reinterpret_cast<const float4*>(src + off * 4);
    __half2 h0 = __floats2half2_rn(v.x, v.y);
    __half2 h1 = __floats2half2_rn(v.z, v.w);
    uint2 o = { *reinterpret_cast<uint32_t*>(&h0), *reinterpret_cast<uint32_t*>(&h1) };
    *reinterpret_cast<uint2*>(dst + off * 4) = o;
}

// ---------------------------------------------------------------------------
// fc1: h0[n(ca), m] = sum_k x[m,k] * w[n,k] + bias[n]  (channel-outer half out)
// ---------------------------------------------------------------------------
__global__ __launch_bounds__(256, 2) void fc1_kernel(const float* __restrict__ bias)
{
    extern __shared__ __align__(16) unsigned char smem_raw[];
    __half* sh = reinterpret_cast<__half*>(smem_raw);
    float*  sf = reinterpret_cast<float*>(smem_raw);

    const int m0  = blockIdx.y * 128;
    const int n0  = blockIdx.x * 128;
    const int tid = threadIdx.x;
    const int wid = tid >> 5;
    const int wm  = wid & 1;
    const int wn  = wid >> 1;

    wmma::fragment<wmma::accumulator, 16, 16, 16, float> acc[4][2];
    #pragma unroll
    for (int i = 0; i < 4; i++)
        #pragma unroll
        for (int j = 0; j < 2; j++)
            wmma::fill_fragment(acc[i][j], 0.0f);

    size_t abase[4], bbase[4];
    int lrow[4], lch[4];
    #pragma unroll
    for (int u = 0; u < 4; u++) {
        int idx = tid + u * 256;
        lrow[u] = idx >> 3;
        lch[u]  = idx & 7;
        int m  = m0 + lrow[u];
        int bt = m / NP;
        int pos = m - bt * NP;
        abase[u] = ((size_t)(bt * Lv + 1 + pos)) * INC;
        bbase[u] = (size_t)(n0 + lrow[u]) * INC;
    }

    constexpr int KT = INC / BK;   // 12

    #pragma unroll
    for (int p = 0; p < 2; p++) {
        __half* st = sh + p * FC1_BUF;
        uint32_t sA = smem_u32(st);
        uint32_t sB = smem_u32(st + FC1_ABUF);
        int k0 = p * BK;
        #pragma unroll
        for (int u = 0; u < 4; u++) {
            uint32_t d = (uint32_t)(lrow[u] * SA + lch[u] * 8) * 2;
            cp16(sA + d, g_xh  + abase[u] + k0 + lch[u] * 8);
            cp16(sB + d, g_w1h + bbase[u] + k0 + lch[u] * 8);
        }
        cp_commit();
    }

    for (int kt = 0; kt < KT; kt++) {
        cp_wait1();
        __syncthreads();

        if (kt + 2 < KT) {
            int k0 = (kt + 2) * BK;
            __half* st = sh + ((kt + 2) % 3) * FC1_BUF;
            uint32_t sA = smem_u32(st);
            uint32_t sB = smem_u32(st + FC1_ABUF);
            #pragma unroll
            for (int u = 0; u < 4; u++) {
                uint32_t d = (uint32_t)(lrow[u] * SA + lch[u] * 8) * 2;
                cp16(sA + d, g_xh  + abase[u] + k0 + lch[u] * 8);
                cp16(sB + d, g_w1h + bbase[u] + k0 + lch[u] * 8);
            }
        }
        cp_commit();

        __half* As = sh + (kt % 3) * FC1_BUF;
        __half* Bs = As + FC1_ABUF;
        #pragma unroll
        for (int ks = 0; ks < BK; ks += 16) {
            wmma::fragment<wmma::matrix_a, 16, 16, 16, __half, wmma::row_major> af[4];
            wmma::fragment<wmma::matrix_b, 16, 16, 16, __half, wmma::col_major> bf[2];
            #pragma unroll
            for (int i = 0; i < 4; i++)
                wmma::load_matrix_sync(af[i], &As[(wm * 64 + i * 16) * SA + ks], SA);
            #pragma unroll
            for (int j = 0; j < 2; j++)
                wmma::load_matrix_sync(bf[j], &Bs[(wn * 32 + j * 16) * SA + ks], SA);
            #pragma unroll
            for (int i = 0; i < 4; i++)
                #pragma unroll
                for (int j = 0; j < 2; j++)
                    wmma::mma_sync(acc[i][j], af[i], bf[j], acc[i][j]);
        }
    }
    __syncthreads();

    // Single-pass epilogue: full 128x128 C staged COL-MAJOR (ldm=132)
    #pragma unroll
    for (int i = 0; i < 4; i++)
        #pragma unroll
        for (int j = 0; j < 2; j++)
            wmma::store_matrix_sync(&sf[(wn * 32 + j * 16) * PCM + wm * 64 + i * 16],
                                    acc[i][j], PCM, wmma::mem_col_major);
    __syncthreads();
    #pragma unroll
    for (int it = 0; it < 64; it++) {
        int e = tid + it * 256;
        int col = e >> 7, r = e & 127;
        int n = n0 + col;
        g_h0h[(size_t)n * MTOT + m0 + r] =
            __float2half(sf[col * PCM + r] + __ldg(&bias[n]));
    }
}

// ---------------------------------------------------------------------------
// Fused convs — thread = spatial pos, rolling 3-plane accumulator.
// 9 LDS per element (was 27), no per-element div/mod, s1 kept in registers.
// ---------------------------------------------------------------------------
__global__ __launch_bounds__(256) void conv_fused_kernel(
    const float* __restrict__ w1, const float* __restrict__ b1,
    const float* __restrict__ w2, const float* __restrict__ b2,
    const float* __restrict__ w3, const float* __restrict__ b3,
    const float* __restrict__ wp, const float* __restrict__ pb)
{
    __shared__ float s0[TILE3D];

    const int tid = threadIdx.x;
    const int ca  = blockIdx.x % CAv;
    const int b   = blockIdx.x / CAv;
    const size_t base = (size_t)ca * MTOT + (size_t)b * TILE3D;

    for (int i = tid * 4; i < TILE3D; i += 1024) {
        uint2 p = *reinterpret_cast<const uint2*>(&g_h0h[base + i]);
        __half2 h0 = *reinterpret_cast<__half2*>(&p.x);
        __half2 h1 = *reinterpret_cast<__half2*>(&p.y);
        float2 f0 = __half22float2(h0);
        float2 f1 = __half22float2(h1);
        s0[i] = f0.x; s0[i + 1] = f0.y; s0[i + 2] = f1.x; s0[i + 3] = f1.y;
    }

    // Combined 27-tap weights (wc[dt*9 + spatial])
    float wc[27];
    #pragma unroll
    for (int j = 0; j < 27; j++) wc[j] = w3[ca * 27 + j];
    #pragma unroll
    for (int j = 0; j < 9; j++)  wc[9 + j] += w2[ca * 9 + j];
    #pragma unroll
    for (int dt = 0; dt < 3; dt++) wc[dt * 9 + 4] += w1[ca * 3 + dt];
    const float bias3 = (b1[ca] + b2[ca] + b3[ca]) * (1.0f / 3.0f);
    const float wp0 = wp[ca * 3], wp1 = wp[ca * 3 + 1], wp2 = wp[ca * 3 + 2];
    const float pbias = pb[ca];

    __syncthreads();

    if (tid < NP) {
        const int pos = tid;
        const int y = pos / Wv;
        const int x = pos - y * Wv;

        // Per-thread constant neighbor offsets + validity
        int  voff[9];
        bool vok[9];
        #pragma unroll
        for (int dy = -1; dy <= 1; dy++)
            #pragma unroll
            for (int dx = -1; dx <= 1; dx++) {
                int j  = (dy + 1) * 3 + (dx + 1);
                int yy = y + dy, xx = x + dx;
                vok[j]  = ((unsigned)yy < (unsigned)Hv) && ((unsigned)xx < (unsigned)Wv);
                voff[j] = yy * Wv + xx;
            }

        float s1r[Tv];
        float a_pm1 = 0.f, a_p0 = 0.f, a_p1 = 0.f;
        #pragma unroll
        for (int p = 0; p < Tv; p++) {
            float v[9];
            #pragma unroll
            for (int j = 0; j < 9; j++)
                v[j] = vok[j] ? s0[p * NP + voff[j]] : 0.f;
            float r0 = 0.f, r1 = 0.f, r2 = 0.f;
            #pragma unroll
            for (int j = 0; j < 9; j++) {
                r0 += wc[j]      * v[j];
                r1 += wc[9 + j]  * v[j];
                r2 += wc[18 + j] * v[j];
            }
            // r0 -> out(p+1), r1 -> out(p), r2 -> out(p-1)
            a_pm1 += r2; a_p0 += r1; a_p1 += r0;
            if (p >= 1)
                s1r[p - 1] = a_pm1 * (1.0f / 3.0f) + bias3 + s0[(p - 1) * NP + pos];
            a_pm1 = a_p0; a_p0 = a_p1; a_p1 = 0.f;
        }
        s1r[Tv - 1] = a_pm1 * (1.0f / 3.0f) + bias3 + s0[(Tv - 1) * NP + pos];

        // proj (temporal 3-tap) + residual, all in registers
        #pragma unroll
        for (int t = 0; t < Tv; t++) {
            float pacc = pbias + wp1 * s1r[t];
            if (t > 0)      pacc += wp0 * s1r[t - 1];
            if (t < Tv - 1) pacc += wp2 * s1r[t + 1];
            g_h2h[base + t * NP + pos] = __float2half(s1r[t] + pacc);
        }
    }
}

// ---------------------------------------------------------------------------
// fc2: out[m, n] = x[m, n] + sum_k h2[k, m] * w[n, k] + bias[n]
// (x residual read from half g_xh — saves fp32 DRAM traffic)
// ---------------------------------------------------------------------------
__global__ __launch_bounds__(256, 2) void fc2_kernel(
    const float* __restrict__ bias,
    float* __restrict__ out)
{
    extern __shared__ __align__(16) unsigned char smem_raw[];
    __half* sh = reinterpret_cast<__half*>(smem_raw);
    float*  sf = reinterpret_cast<float*>(smem_raw);

    const int m0  = blockIdx.y * 128;
    const int n0  = blockIdx.x * 128;
    const int tid = threadIdx.x;
    const int wid = tid >> 5;
    const int wm  = wid & 1;
    const int wn  = wid >> 1;

    wmma::fragment<wmma::accumulator, 16, 16, 16, float> acc[4][2];
    #pragma unroll
    for (int i = 0; i < 4; i++)
        #pragma unroll
        for (int j = 0; j < 2; j++)
            wmma::fill_fragment(acc[i][j], 0.0f);

    int akr[4], amc[4], brow[4], bch[4];
    size_t bbase[4];
    #pragma unroll
    for (int u = 0; u < 4; u++) {
        int idx = tid + u * 256;
        akr[u] = idx >> 4;
        amc[u] = idx & 15;
        brow[u] = idx >> 3;
        bch[u]  = idx & 7;
        bbase[u] = (size_t)(n0 + brow[u]) * CAv;
    }

    constexpr int KT = CAv / BK;   // 6

    #pragma unroll
    for (int p = 0; p < 2; p++) {
        __half* st = sh + p * FC2_BUF;
        uint32_t sA = smem_u32(st);
        uint32_t sB = smem_u32(st + FC2_ABUF);
        int k0 = p * BK;
        #pragma unroll
        for (int u = 0; u < 4; u++) {
            cp16(sA + (uint32_t)(akr[u] * SAT + amc[u] * 8) * 2,
                 g_h2h + (size_t)(k0 + akr[u]) * MTOT + m0 + amc[u] * 8);
            cp16(sB + (uint32_t)(brow[u] * SA + bch[u] * 8) * 2,
                 g_w2h + bbase[u] + k0 + bch[u] * 8);
        }
        cp_commit();
    }

    for (int kt = 0; kt < KT; kt++) {
        cp_wait1();
        __syncthreads();

        if (kt + 2 < KT) {
            int k0 = (kt + 2) * BK;
            __half* st = sh + ((kt + 2) % 3) * FC2_BUF;
            uint32_t sA = smem_u32(st);
            uint32_t sB = smem_u32(st + FC2_ABUF);
            #pragma unroll
            for (int u = 0; u < 4; u++) {
                cp16(sA + (uint32_t)(akr[u] * SAT + amc[u] * 8) * 2,
                     g_h2h + (size_t)(k0 + akr[u]) * MTOT + m0 + amc[u] * 8);
                cp16(sB + (uint32_t)(brow[u] * SA + bch[u] * 8) * 2,
                     g_w2h + bbase[u] + k0 + bch[u] * 8);
            }
        }
        cp_commit();

        __half* As = sh + (kt % 3) * FC2_BUF;
        __half* Bs = As + FC2_ABUF;
        #pragma unroll
        for (int ks = 0; ks < BK; ks += 16) {
            wmma::fragment<wmma::matrix_a, 16, 16, 16, __half, wmma::col_major> af[4];
            wmma::fragment<wmma::matrix_b, 16, 16, 16, __half, wmma::col_major> bf[2];
            #pragma unroll
            for (int i = 0; i < 4; i++)
                wmma::load_matrix_sync(af[i], &As[ks * SAT + wm * 64 + i * 16], SAT);
            #pragma unroll
            for (int j = 0; j < 2; j++)
                wmma::load_matrix_sync(bf[j], &Bs[(wn * 32 + j * 16) * SA + ks], SA);
            #pragma unroll
            for (int i = 0; i < 4; i++)
                #pragma unroll
                for (int j = 0; j < 2; j++)
                    wmma::mma_sync(acc[i][j], af[i], bf[j], acc[i][j]);
        }
    }
    __syncthreads();

    // Single-pass epilogue: full 128x128 C staged ROW-MAJOR (ldm=132)
    #pragma unroll
    for (int i = 0; i < 4; i++)
        #pragma unroll
        for (int j = 0; j < 2; j++)
            wmma::store_matrix_sync(&sf[(wm * 64 + i * 16) * PCM + wn * 32 + j * 16],
                                    acc[i][j], PCM, wmma::mem_row_major);
    __syncthreads();
    #pragma unroll
    for (int it = 0; it < 64; it++) {
        int e = tid + it * 256;
        int c = e & 127, r = e >> 7;
        int m = m0 + r;
        int bt = m / NP;
        int pos = m - bt * NP;
        int n = n0 + c;
        size_t off = ((size_t)(bt * Lv + 1 + pos)) * INC + n;
        out[off] = __half2float(g_xh[off]) + sf[r * PCM + c] + __ldg(&bias[n]);
    }
}

// ---------------------------------------------------------------------------
extern "C" void kernel_launch(void* const* d_in, const int* in_sizes, int n_in,
                              void* d_out, int out_size)
{
    const float* x     = (const float*)d_in[0];
    const float* fc1_w = (const float*)d_in[1];
    const float* fc1_b = (const float*)d_in[2];
    const float* c1w   = (const float*)d_in[3];
    const float* c1b   = (const float*)d_in[4];
    const float* c2w   = (const float*)d_in[5];
    const float* c2b   = (const float*)d_in[6];
    const float* c3w   = (const float*)d_in[7];
    const float* c3b   = (const float*)d_in[8];
    const float* pw    = (const float*)d_in[9];
    const float* pb    = (const float*)d_in[10];
    const float* fc2_w = (const float*)d_in[11];
    const float* fc2_b = (const float*)d_in[12];
    float* out = (float*)d_out;

    cudaFuncSetAttribute(fc1_kernel, cudaFuncAttributeMaxDynamicSharedMemorySize, FC1_SMEM);
    cudaFuncSetAttribute(fc2_kernel, cudaFuncAttributeMaxDynamicSharedMemorySize, FC2_SMEM);

    int ncvt = NX4 + 2 * NW4 + NC4;
    cvt_all_kernel<<<(ncvt + 255) / 256, 256>>>(x, fc1_w, fc2_w, out);

    dim3 g1(CAv / 128, MTOT / 128);   // (3, 196)
    fc1_kernel<<<g1, 256, FC1_SMEM>>>(fc1_b);

    conv_fused_kernel<<<CAv * (BTv / Tv), 256>>>(c1w, c1b, c2w, c2b, c3w, c3b, pw, pb);

    dim3 g2(INC / 128, MTOT / 128);   // (6, 196)
    fc2_kernel<<<g2, 256, FC2_SMEM>>>(fc2_b, out);
}

// round 17
// speedup vs baseline: 1.5444x; 1.5444x over previous
#include <cuda_runtime.h>
#include <cuda_fp16.h>
#include <mma.h>
#include <cstdint>

using namespace nvcuda;

constexpr int INC  = 768;
constexpr int CAv  = 384;
constexpr int BTv  = 128;
constexpr int Tv   = 16;
constexpr int Hv   = 14;
constexpr int Wv   = 14;
constexpr int Lv   = 197;
constexpr int NP   = 196;
constexpr int MTOT = BTv * NP;       // 25088
constexpr int TILE3D = Tv * NP;      // 3136

// Scratch (device globals — no runtime allocation allowed)
__device__ __half g_xh[(size_t)BTv * Lv * INC];
__device__ __half g_w1h[(size_t)CAv * INC];
__device__ __half g_w2h[(size_t)INC * CAv];
__device__ __half g_h0h[(size_t)CAv * MTOT];       // channel-outer [ca][m]
__device__ __half g_h2h[(size_t)CAv * MTOT];       // channel-outer [ca][m]

// GEMM tiling: BM=BN=128, BK=64, 3-stage cp.async pipeline
#define BK 64
#define SA 72     // half-row stride for [*][64]-half K tiles (144B)
#define SAT 136   // half-row stride for fc2 transposed-A [64][128]
#define PCM 132   // C staging ldm (floats, mult of 4)

constexpr int FC1_ABUF = 128 * SA;                 // 9216 halves
constexpr int FC1_BUF  = 2 * FC1_ABUF;             // 18432 halves/stage
constexpr int FC1_SMEM = 3 * FC1_BUF * 2;          // 110592 B
constexpr int FC2_ABUF = BK * SAT;                 // 8704 halves
constexpr int FC2_BBUF = 128 * SA;                 // 9216 halves
constexpr int FC2_BUF  = FC2_ABUF + FC2_BBUF;      // 17920 halves/stage
constexpr int FC2_SMEM = 3 * FC2_BUF * 2;          // 107520 B

__device__ __forceinline__ void cp16(uint32_t dst, const void* src) {
    asm volatile("cp.async.cg.shared.global [%0], [%1], 16;\n" :: "r"(dst), "l"(src));
}
__device__ __forceinline__ void cp_commit() { asm volatile("cp.async.commit_group;\n"); }
__device__ __forceinline__ void cp_wait1()  { asm volatile("cp.async.wait_group 1;\n"); }
__device__ __forceinline__ uint32_t smem_u32(const void* p) {
    return (uint32_t)__cvta_generic_to_shared(p);
}

// ---------------------------------------------------------------------------
// Merged converter + CLS copy: x->half, w1->half, w2->half, out[CLS]=x[CLS]
// ---------------------------------------------------------------------------
constexpr int NX4 = BTv * Lv * INC / 4;
constexpr int NW4 = CAv * INC / 4;
constexpr int NC4 = BTv * INC / 4;

__global__ __launch_bounds__(256) void cvt_all_kernel(
    const float* __restrict__ x, const float* __restrict__ w1,
    const float* __restrict__ w2, float* __restrict__ out)
{
    int i = blockIdx.x * 256 + threadIdx.x;
    const float* src; __half* dst; size_t off;
    if (i < NX4)                { src = x;  dst = g_xh;  off = (size_t)i; }
    else if (i < NX4 + NW4)     { src = w1; dst = g_w1h; off = (size_t)(i - NX4); }
    else if (i < NX4 + 2 * NW4) { src = w2; dst = g_w2h; off = (size_t)(i - NX4 - NW4); }
    else if (i < NX4 + 2 * NW4 + NC4) {
        int j  = i - NX4 - 2 * NW4;
        int bt = j / (INC / 4);
        int c4 = j - bt * (INC / 4);
        size_t o = (size_t)bt * Lv * INC + (size_t)c4 * 4;
        *reinterpret_cast<float4*>(out + o) = *reinterpret_cast<const float4*>(x + o);
        return;
    }
    else return;
    float4 v = *reinterpret_cast<const float4*>(src + off * 4);
    __half2 h0 = __floats2half2_rn(v.x, v.y);
    __half2 h1 = __floats2half2_rn(v.z, v.w);
    uint2 o = { *reinterpret_cast<uint32_t*>(&h0), *reinterpret_cast<uint32_t*>(&h1) };
    *reinterpret_cast<uint2*>(dst + off * 4) = o;
}

// ---------------------------------------------------------------------------
// fc1: h0[n(ca), m] = sum_k x[m,k] * w[n,k] + bias[n]  (channel-outer half out)
// ---------------------------------------------------------------------------
__global__ __launch_bounds__(256, 2) void fc1_kernel(const float* __restrict__ bias)
{
    extern __shared__ __align__(16) unsigned char smem_raw[];
    __half* sh = reinterpret_cast<__half*>(smem_raw);
    float*  sf = reinterpret_cast<float*>(smem_raw);

    const int m0  = blockIdx.y * 128;
    const int n0  = blockIdx.x * 128;
    const int tid = threadIdx.x;
    const int wid = tid >> 5;
    const int wm  = wid & 1;
    const int wn  = wid >> 1;

    wmma::fragment<wmma::accumulator, 16, 16, 16, float> acc[4][2];
    #pragma unroll
    for (int i = 0; i < 4; i++)
        #pragma unroll
        for (int j = 0; j < 2; j++)
            wmma::fill_fragment(acc[i][j], 0.0f);

    size_t abase[4], bbase[4];
    int lrow[4], lch[4];
    #pragma unroll
    for (int u = 0; u < 4; u++) {
        int idx = tid + u * 256;
        lrow[u] = idx >> 3;
        lch[u]  = idx & 7;
        int m  = m0 + lrow[u];
        int bt = m / NP;
        int pos = m - bt * NP;
        abase[u] = ((size_t)(bt * Lv + 1 + pos)) * INC;
        bbase[u] = (size_t)(n0 + lrow[u]) * INC;
    }

    constexpr int KT = INC / BK;   // 12

    #pragma unroll
    for (int p = 0; p < 2; p++) {
        __half* st = sh + p * FC1_BUF;
        uint32_t sA = smem_u32(st);
        uint32_t sB = smem_u32(st + FC1_ABUF);
        int k0 = p * BK;
        #pragma unroll
        for (int u = 0; u < 4; u++) {
            uint32_t d = (uint32_t)(lrow[u] * SA + lch[u] * 8) * 2;
            cp16(sA + d, g_xh  + abase[u] + k0 + lch[u] * 8);
            cp16(sB + d, g_w1h + bbase[u] + k0 + lch[u] * 8);
        }
        cp_commit();
    }

    for (int kt = 0; kt < KT; kt++) {
        cp_wait1();
        __syncthreads();

        if (kt + 2 < KT) {
            int k0 = (kt + 2) * BK;
            __half* st = sh + ((kt + 2) % 3) * FC1_BUF;
            uint32_t sA = smem_u32(st);
            uint32_t sB = smem_u32(st + FC1_ABUF);
            #pragma unroll
            for (int u = 0; u < 4; u++) {
                uint32_t d = (uint32_t)(lrow[u] * SA + lch[u] * 8) * 2;
                cp16(sA + d, g_xh  + abase[u] + k0 + lch[u] * 8);
                cp16(sB + d, g_w1h + bbase[u] + k0 + lch[u] * 8);
            }
        }
        cp_commit();

        __half* As = sh + (kt % 3) * FC1_BUF;
        __half* Bs = As + FC1_ABUF;
        #pragma unroll
        for (int ks = 0; ks < BK; ks += 16) {
            wmma::fragment<wmma::matrix_a, 16, 16, 16, __half, wmma::row_major> af[4];
            wmma::fragment<wmma::matrix_b, 16, 16, 16, __half, wmma::col_major> bf[2];
            #pragma unroll
            for (int i = 0; i < 4; i++)
                wmma::load_matrix_sync(af[i], &As[(wm * 64 + i * 16) * SA + ks], SA);
            #pragma unroll
            for (int j = 0; j < 2; j++)
                wmma::load_matrix_sync(bf[j], &Bs[(wn * 32 + j * 16) * SA + ks], SA);
            #pragma unroll
            for (int i = 0; i < 4; i++)
                #pragma unroll
                for (int j = 0; j < 2; j++)
                    wmma::mma_sync(acc[i][j], af[i], bf[j], acc[i][j]);
        }
    }
    __syncthreads();

    // Single-pass epilogue: full 128x128 C staged COL-MAJOR (ldm=132)
    #pragma unroll
    for (int i = 0; i < 4; i++)
        #pragma unroll
        for (int j = 0; j < 2; j++)
            wmma::store_matrix_sync(&sf[(wn * 32 + j * 16) * PCM + wm * 64 + i * 16],
                                    acc[i][j], PCM, wmma::mem_col_major);
    __syncthreads();
    #pragma unroll
    for (int it = 0; it < 64; it++) {
        int e = tid + it * 256;
        int col = e >> 7, r = e & 127;
        int n = n0 + col;
        g_h0h[(size_t)n * MTOT + m0 + r] =
            __float2half(sf[col * PCM + r] + __ldg(&bias[n]));
    }
}

// ---------------------------------------------------------------------------
// Fused convs — thread = spatial pos, rolling 3-plane accumulator.
// ---------------------------------------------------------------------------
__global__ __launch_bounds__(256) void conv_fused_kernel(
    const float* __restrict__ w1, const float* __restrict__ b1,
    const float* __restrict__ w2, const float* __restrict__ b2,
    const float* __restrict__ w3, const float* __restrict__ b3,
    const float* __restrict__ wp, const float* __restrict__ pb)
{
    __shared__ float s0[TILE3D];

    const int tid = threadIdx.x;
    const int ca  = blockIdx.x % CAv;
    const int b   = blockIdx.x / CAv;
    const size_t base = (size_t)ca * MTOT + (size_t)b * TILE3D;

    for (int i = tid * 4; i < TILE3D; i += 1024) {
        uint2 p = *reinterpret_cast<const uint2*>(&g_h0h[base + i]);
        __half2 h0 = *reinterpret_cast<__half2*>(&p.x);
        __half2 h1 = *reinterpret_cast<__half2*>(&p.y);
        float2 f0 = __half22float2(h0);
        float2 f1 = __half22float2(h1);
        s0[i] = f0.x; s0[i + 1] = f0.y; s0[i + 2] = f1.x; s0[i + 3] = f1.y;
    }

    float wc[27];
    #pragma unroll
    for (int j = 0; j < 27; j++) wc[j] = w3[ca * 27 + j];
    #pragma unroll
    for (int j = 0; j < 9; j++)  wc[9 + j] += w2[ca * 9 + j];
    #pragma unroll
    for (int dt = 0; dt < 3; dt++) wc[dt * 9 + 4] += w1[ca * 3 + dt];
    const float bias3 = (b1[ca] + b2[ca] + b3[ca]) * (1.0f / 3.0f);
    const float wp0 = wp[ca * 3], wp1 = wp[ca * 3 + 1], wp2 = wp[ca * 3 + 2];
    const float pbias = pb[ca];

    __syncthreads();

    if (tid < NP) {
        const int pos = tid;
        const int y = pos / Wv;
        const int x = pos - y * Wv;

        int  voff[9];
        bool vok[9];
        #pragma unroll
        for (int dy = -1; dy <= 1; dy++)
            #pragma unroll
            for (int dx = -1; dx <= 1; dx++) {
                int j  = (dy + 1) * 3 + (dx + 1);
                int yy = y + dy, xx = x + dx;
                vok[j]  = ((unsigned)yy < (unsigned)Hv) && ((unsigned)xx < (unsigned)Wv);
                voff[j] = yy * Wv + xx;
            }

        float s1r[Tv];
        float a_pm1 = 0.f, a_p0 = 0.f, a_p1 = 0.f;
        #pragma unroll
        for (int p = 0; p < Tv; p++) {
            float v[9];
            #pragma unroll
            for (int j = 0; j < 9; j++)
                v[j] = vok[j] ? s0[p * NP + voff[j]] : 0.f;
            float r0 = 0.f, r1 = 0.f, r2 = 0.f;
            #pragma unroll
            for (int j = 0; j < 9; j++) {
                r0 += wc[j]      * v[j];
                r1 += wc[9 + j]  * v[j];
                r2 += wc[18 + j] * v[j];
            }
            a_pm1 += r2; a_p0 += r1; a_p1 += r0;
            if (p >= 1)
                s1r[p - 1] = a_pm1 * (1.0f / 3.0f) + bias3 + s0[(p - 1) * NP + pos];
            a_pm1 = a_p0; a_p0 = a_p1; a_p1 = 0.f;
        }
        s1r[Tv - 1] = a_pm1 * (1.0f / 3.0f) + bias3 + s0[(Tv - 1) * NP + pos];

        #pragma unroll
        for (int t = 0; t < Tv; t++) {
            float pacc = pbias + wp1 * s1r[t];
            if (t > 0)      pacc += wp0 * s1r[t - 1];
            if (t < Tv - 1) pacc += wp2 * s1r[t + 1];
            g_h2h[base + t * NP + pos] = __float2half(s1r[t] + pacc);
        }
    }
}

// ---------------------------------------------------------------------------
// fc2: out[m, n] = x[m, n] + sum_k h2[k, m] * w[n, k] + bias[n]
// (x residual via __restrict__ parameter — REVERTED from g_xh; alias-safe)
// ---------------------------------------------------------------------------
__global__ __launch_bounds__(256, 2) void fc2_kernel(
    const float* __restrict__ bias,
    const float* __restrict__ x,
    float* __restrict__ out)
{
    extern __shared__ __align__(16) unsigned char smem_raw[];
    __half* sh = reinterpret_cast<__half*>(smem_raw);
    float*  sf = reinterpret_cast<float*>(smem_raw);

    const int m0  = blockIdx.y * 128;
    const int n0  = blockIdx.x * 128;
    const int tid = threadIdx.x;
    const int wid = tid >> 5;
    const int wm  = wid & 1;
    const int wn  = wid >> 1;

    wmma::fragment<wmma::accumulator, 16, 16, 16, float> acc[4][2];
    #pragma unroll
    for (int i = 0; i < 4; i++)
        #pragma unroll
        for (int j = 0; j < 2; j++)
            wmma::fill_fragment(acc[i][j], 0.0f);

    int akr[4], amc[4], brow[4], bch[4];
    size_t bbase[4];
    #pragma unroll
    for (int u = 0; u < 4; u++) {
        int idx = tid + u * 256;
        akr[u] = idx >> 4;
        amc[u] = idx & 15;
        brow[u] = idx >> 3;
        bch[u]  = idx & 7;
        bbase[u] = (size_t)(n0 + brow[u]) * CAv;
    }

    constexpr int KT = CAv / BK;   // 6

    #pragma unroll
    for (int p = 0; p < 2; p++) {
        __half* st = sh + p * FC2_BUF;
        uint32_t sA = smem_u32(st);
        uint32_t sB = smem_u32(st + FC2_ABUF);
        int k0 = p * BK;
        #pragma unroll
        for (int u = 0; u < 4; u++) {
            cp16(sA + (uint32_t)(akr[u] * SAT + amc[u] * 8) * 2,
                 g_h2h + (size_t)(k0 + akr[u]) * MTOT + m0 + amc[u] * 8);
            cp16(sB + (uint32_t)(brow[u] * SA + bch[u] * 8) * 2,
                 g_w2h + bbase[u] + k0 + bch[u] * 8);
        }
        cp_commit();
    }

    for (int kt = 0; kt < KT; kt++) {
        cp_wait1();
        __syncthreads();

        if (kt + 2 < KT) {
            int k0 = (kt + 2) * BK;
            __half* st = sh + ((kt + 2) % 3) * FC2_BUF;
            uint32_t sA = smem_u32(st);
            uint32_t sB = smem_u32(st + FC2_ABUF);
            #pragma unroll
            for (int u = 0; u < 4; u++) {
                cp16(sA + (uint32_t)(akr[u] * SAT + amc[u] * 8) * 2,
                     g_h2h + (size_t)(k0 + akr[u]) * MTOT + m0 + amc[u] * 8);
                cp16(sB + (uint32_t)(brow[u] * SA + bch[u] * 8) * 2,
                     g_w2h + bbase[u] + k0 + bch[u] * 8);
            }
        }
        cp_commit();

        __half* As = sh + (kt % 3) * FC2_BUF;
        __half* Bs = As + FC2_ABUF;
        #pragma unroll
        for (int ks = 0; ks < BK; ks += 16) {
            wmma::fragment<wmma::matrix_a, 16, 16, 16, __half, wmma::col_major> af[4];
            wmma::fragment<wmma::matrix_b, 16, 16, 16, __half, wmma::col_major> bf[2];
            #pragma unroll
            for (int i = 0; i < 4; i++)
                wmma::load_matrix_sync(af[i], &As[ks * SAT + wm * 64 + i * 16], SAT);
            #pragma unroll
            for (int j = 0; j < 2; j++)
                wmma::load_matrix_sync(bf[j], &Bs[(wn * 32 + j * 16) * SA + ks], SA);
            #pragma unroll
            for (int i = 0; i < 4; i++)
                #pragma unroll
                for (int j = 0; j < 2; j++)
                    wmma::mma_sync(acc[i][j], af[i], bf[j], acc[i][j]);
        }
    }
    __syncthreads();

    // Single-pass epilogue: full 128x128 C staged ROW-MAJOR (ldm=132)
    #pragma unroll
    for (int i = 0; i < 4; i++)
        #pragma unroll
        for (int j = 0; j < 2; j++)
            wmma::store_matrix_sync(&sf[(wm * 64 + i * 16) * PCM + wn * 32 + j * 16],
                                    acc[i][j], PCM, wmma::mem_row_major);
    __syncthreads();
    #pragma unroll
    for (int it = 0; it < 64; it++) {
        int e = tid + it * 256;
        int c = e & 127, r = e >> 7;
        int m = m0 + r;
        int bt = m / NP;
        int pos = m - bt * NP;
        int n = n0 + c;
        size_t off = ((size_t)(bt * Lv + 1 + pos)) * INC + n;
        out[off] = x[off] + sf[r * PCM + c] + __ldg(&bias[n]);
    }
}

// ---------------------------------------------------------------------------
extern "C" void kernel_launch(void* const* d_in, const int* in_sizes, int n_in,
                              void* d_out, int out_size)
{
    const float* x     = (const float*)d_in[0];
    const float* fc1_w = (const float*)d_in[1];
    const float* fc1_b = (const float*)d_in[2];
    const float* c1w   = (const float*)d_in[3];
    const float* c1b   = (const float*)d_in[4];
    const float* c2w   = (const float*)d_in[5];
    const float* c2b   = (const float*)d_in[6];
    const float* c3w   = (const float*)d_in[7];
    const float* c3b   = (const float*)d_in[8];
    const float* pw    = (const float*)d_in[9];
    const float* pb    = (const float*)d_in[10];
    const float* fc2_w = (const float*)d_in[11];
    const float* fc2_b = (const float*)d_in[12];
    float* out = (float*)d_out;

    cudaFuncSetAttribute(fc1_kernel, cudaFuncAttributeMaxDynamicSharedMemorySize, FC1_SMEM);
    cudaFuncSetAttribute(fc2_kernel, cudaFuncAttributeMaxDynamicSharedMemorySize, FC2_SMEM);

    int ncvt = NX4 + 2 * NW4 + NC4;
    cvt_all_kernel<<<(ncvt + 255) / 256, 256>>>(x, fc1_w, fc2_w, out);

    dim3 g1(CAv / 128, MTOT / 128);   // (3, 196)
    fc1_kernel<<<g1, 256, FC1_SMEM>>>(fc1_b);

    conv_fused_kernel<<<CAv * (BTv / Tv), 256>>>(c1w, c1b, c2w, c2b, c3w, c3b, pw, pb);

    dim3 g2(INC / 128, MTOT / 128);   // (6, 196)
    fc2_kernel<<<g2, 256, FC2_SMEM>>>(fc2_b, x, out);
}